// round 1
// baseline (speedup 1.0000x reference)
#include <cuda_runtime.h>
#include <cstdint>

// SpikeFP8MulToFP32:
//   A, B: [N, 8] float 0/1 bit-vectors of fp8 e4m3 (order S,E3..E0,M2,M1,M0)
//   out : [N, 32] float 0/1 bit-vector of fp32(A_val * B_val), MSB (sign) first.
//
// Pure streaming problem: 256 MB in, 512 MB out. Strategy:
//   - 1 thread = 1 row, vectorized LDG.128 inputs (coalesced)
//   - decode + 1 IEEE FMUL (exact; preserves signed zero)
//   - stage fp32 product words in SMEM, then coalesced STG.128 output
//     (direct per-row stores would scatter 16B chunks across 32 lines/warp)

static __device__ __forceinline__ uint32_t bit_of(float f) {
    // inputs are exactly 0.0f (0x00000000) or 1.0f (0x3F800000): test bit 23
    return (__float_as_uint(f) >> 23) & 1u;
}

static __device__ __forceinline__ float decode_e4m3(float4 lo, float4 hi) {
    // lo = {S, E3, E2, E1}, hi = {E0, M2, M1, M0}
    uint32_t s = bit_of(lo.x);
    uint32_t e = (bit_of(lo.y) << 3) | (bit_of(lo.z) << 2) |
                 (bit_of(lo.w) << 1) |  bit_of(hi.x);
    uint32_t m = (bit_of(hi.y) << 2) | (bit_of(hi.z) << 1) | bit_of(hi.w);
    // normal:    (8+m) * 2^(e-10)
    // subnormal:  m    * 2^(-9)
    uint32_t M = e ? (8u + m) : m;
    int      E = e ? ((int)e - 10) : -9;
    float mag = (float)(int)M * __int_as_float((E + 127) << 23);
    // OR the sign in so M==0 yields a correctly signed zero (-0.0 matters:
    // the reference's fp32 bitcast exposes the sign bit of zero products)
    return __uint_as_float(__float_as_uint(mag) | (s << 31));
}

__global__ void __launch_bounds__(256)
spike_fp8_mul_kernel(const float4* __restrict__ A4,
                     const float4* __restrict__ B4,
                     float4* __restrict__ out4,
                     int nrows) {
    __shared__ uint32_t sh[256];

    const int tid = threadIdx.x;
    const int row = blockIdx.x * 256 + tid;

    uint32_t pbits = 0;
    if (row < nrows) {
        // each row = 8 floats = 2 float4
        float4 a0 = __ldcs(&A4[2 * row + 0]);
        float4 a1 = __ldcs(&A4[2 * row + 1]);
        float4 b0 = __ldcs(&B4[2 * row + 0]);
        float4 b1 = __ldcs(&B4[2 * row + 1]);
        float va = decode_e4m3(a0, a1);
        float vb = decode_e4m3(b0, b1);
        pbits = __float_as_uint(va * vb);   // exact in fp32; IEEE sign-of-zero
    }
    sh[tid] = pbits;
    __syncthreads();

    // Block writes 256 rows * 32 floats = 2048 float4, fully coalesced.
    // float4 q covers output floats [4q .. 4q+3] of this block's tile:
    //   local row = q>>3, bit group g = q&7, out[j] = bit (31-j) of p.
    const int rows_left = nrows - blockIdx.x * 256;      // >0
    const int q_limit   = rows_left >= 256 ? 2048 : rows_left * 8;
    float4* blk_out = out4 + (size_t)blockIdx.x * 2048;

    const int g_shift = 28 - ((tid & 7) << 2);           // invariant over k

#pragma unroll
    for (int k = 0; k < 8; k++) {
        int q = (k << 8) + tid;
        if (q < q_limit) {
            uint32_t p = sh[q >> 3];                     // 8-lane broadcast
            uint32_t t = p >> g_shift;                   // bits [31-4g .. 28-4g] in t[3..0]
            float4 v;
            v.x = __uint_as_float(((t >> 3) & 1u) * 0x3F800000u);
            v.y = __uint_as_float(((t >> 2) & 1u) * 0x3F800000u);
            v.z = __uint_as_float(((t >> 1) & 1u) * 0x3F800000u);
            v.w = __uint_as_float(( t        & 1u) * 0x3F800000u);
            __stcs(&blk_out[q], v);
        }
    }
}

extern "C" void kernel_launch(void* const* d_in, const int* in_sizes, int n_in,
                              void* d_out, int out_size) {
    const float4* A4 = (const float4*)d_in[0];
    const float4* B4 = (const float4*)d_in[1];
    float4* out4 = (float4*)d_out;

    int nrows = in_sizes[0] / 8;
    int blocks = (nrows + 255) / 256;
    spike_fp8_mul_kernel<<<blocks, 256>>>(A4, B4, out4, nrows);
}